// round 1
// baseline (speedup 1.0000x reference)
#include <cuda_runtime.h>
#include <cstdint>

// ---------------- problem constants (shapes fixed by the dataset) -----------
#define DN   128          // node feature dim / output cols
#define DE   64           // edge feature dim
#define KIN  192          // DN + DE
#define NMAX 50000        // nodes

// ---------------- device scratch (allocation-free) --------------------------
__device__ float g_sums[(size_t)NMAX * DN];   // scatter-sum accumulator
__device__ float g_cnt[NMAX];                 // per-node edge counts
__device__ int   g_is64;                      // edge_index dtype flag

// ---------------- helpers ----------------------------------------------------
__device__ __forceinline__ float lrelu(float v) { return v > 0.f ? v : 0.01f * v; }

// LayerNorm(128) + LeakyReLU on 4 per-lane values; cols of one row live in one warp.
__device__ __forceinline__ void ln_leaky4(float& v0, float& v1, float& v2, float& v3,
                                          float4 bb, float4 gg, float4 beb)
{
    v0 += bb.x; v1 += bb.y; v2 += bb.z; v3 += bb.w;
    float s = v0 + v1 + v2 + v3;
    float q = fmaf(v0, v0, fmaf(v1, v1, fmaf(v2, v2, v3 * v3)));
#pragma unroll
    for (int o = 16; o > 0; o >>= 1) {
        s += __shfl_xor_sync(0xffffffffu, s, o);
        q += __shfl_xor_sync(0xffffffffu, q, o);
    }
    const float inv = 0.0078125f;           // 1/128
    float mean = s * inv;
    float var  = fmaf(q, inv, -mean * mean);
    float rstd = rsqrtf(var + 1e-5f);
    v0 = lrelu(fmaf((v0 - mean) * rstd, gg.x, beb.x));
    v1 = lrelu(fmaf((v1 - mean) * rstd, gg.y, beb.y));
    v2 = lrelu(fmaf((v2 - mean) * rstd, gg.z, beb.z));
    v3 = lrelu(fmaf((v3 - mean) * rstd, gg.w, beb.w));
}

// Packed-f32x2 GEMM core: RR rows per warp, K inner dim, 4 cols/lane (2 f32x2 accs).
// sW is [K][128] row-major in shared; A rows are broadcast reads from shared.
template <int K, int RR>
__device__ __forceinline__ void gemm_rows(const float* __restrict__ arow,
                                          const float* __restrict__ sW,
                                          int c0,
                                          unsigned long long* acc0,
                                          unsigned long long* acc1)
{
#pragma unroll
    for (int r = 0; r < RR; ++r) { acc0[r] = 0ULL; acc1[r] = 0ULL; }

#pragma unroll 2
    for (int k = 0; k < K; k += 2) {
        ulonglong2 b0 = *(const ulonglong2*)(sW + (size_t)(k + 0) * DN + c0);
        ulonglong2 b1 = *(const ulonglong2*)(sW + (size_t)(k + 1) * DN + c0);
#pragma unroll
        for (int r = 0; r < RR; ++r) {
            float2 a = *(const float2*)(arow + (size_t)r * K + k);
            unsigned long long ax, ay;
            asm("mov.b64 %0, {%1, %1};" : "=l"(ax) : "f"(a.x));
            asm("mov.b64 %0, {%1, %1};" : "=l"(ay) : "f"(a.y));
            asm("fma.rn.f32x2 %0, %1, %2, %0;" : "+l"(acc0[r]) : "l"(ax), "l"(b0.x));
            asm("fma.rn.f32x2 %0, %1, %2, %0;" : "+l"(acc1[r]) : "l"(ax), "l"(b0.y));
            asm("fma.rn.f32x2 %0, %1, %2, %0;" : "+l"(acc0[r]) : "l"(ay), "l"(b1.x));
            asm("fma.rn.f32x2 %0, %1, %2, %0;" : "+l"(acc1[r]) : "l"(ay), "l"(b1.y));
        }
    }
}

__device__ __forceinline__ void unpack2(unsigned long long p, float& lo, float& hi)
{
    asm("mov.b64 {%0, %1}, %2;" : "=f"(lo), "=f"(hi) : "l"(p));
}

// ---------------- kernel 0: edge_index dtype detection ----------------------
// int64 little-endian: odd 32-bit words are high halves == 0 (indices < 2^31).
// int32: odd words are real indices, some nonzero with overwhelming probability.
__global__ void detect_kernel(const unsigned* __restrict__ w, int E)
{
    __shared__ unsigned accsh;
    if (threadIdx.x == 0) accsh = 0u;
    __syncthreads();
    int nscan = 4096;
    if (2 * nscan > 2 * E) nscan = E;   // stay within guaranteed buffer (2E words)
    unsigned nz = 0;
    for (int i = threadIdx.x; i < nscan; i += blockDim.x) nz |= w[2 * i + 1];
#pragma unroll
    for (int o = 16; o > 0; o >>= 1) nz |= __shfl_xor_sync(0xffffffffu, nz, o);
    if ((threadIdx.x & 31) == 0) atomicOr(&accsh, nz);
    __syncthreads();
    if (threadIdx.x == 0) g_is64 = (accsh == 0u) ? 1 : 0;
}

// ---------------- kernel 1: zero accumulators --------------------------------
__global__ void zero_kernel(int N)
{
    int tid = blockIdx.x * blockDim.x + threadIdx.x;
    int stride = gridDim.x * blockDim.x;
    float4 z = make_float4(0.f, 0.f, 0.f, 0.f);
    float4* s4 = (float4*)g_sums;
    int n4 = N * (DN / 4);
    for (int i = tid; i < n4; i += stride) s4[i] = z;
    for (int i = tid; i < N; i += stride) g_cnt[i] = 0.f;
}

// ---------------- kernel 2: fused edge MLP + LN + LeakyReLU + scatter --------
// Persistent: grid = 148 (1 block/SM, 192KB smem). Block = 256 threads (8 warps).
// Tile = 128 edges; each warp owns 16 edges, each lane owns 4 output columns.
#define E_R     16
#define E_TILE  128

__global__ void __launch_bounds__(256, 1) edge_kernel(
    const float* __restrict__ x, const void* __restrict__ eidx,
    const float* __restrict__ ea, const float* __restrict__ W1,
    const float* __restrict__ b1, const float* __restrict__ g1,
    const float* __restrict__ be1, int N, int E)
{
    extern __shared__ float smem[];
    float* sW = smem;                    // KIN * DN floats (96 KB)
    float* sA = smem + KIN * DN;         // E_TILE * KIN floats (96 KB)

    int tid  = threadIdx.x;
    int wid  = tid >> 5;
    int lane = tid & 31;
    int c0   = lane * 4;

    // stage W1 once (persistent block)
    for (int i = tid * 4; i < KIN * DN; i += blockDim.x * 4)
        *(float4*)&sW[i] = *(const float4*)&W1[i];

    float4 bb  = *(const float4*)&b1[c0];
    float4 gg  = *(const float4*)&g1[c0];
    float4 beb = *(const float4*)&be1[c0];

    const int is64 = g_is64;
    const long long* ei64 = (const long long*)eidx;
    const int*       ei32 = (const int*)eidx;

    int ntiles = (E + E_TILE - 1) / E_TILE;
    for (int t = blockIdx.x; t < ntiles; t += gridDim.x) {
        int e0 = t * E_TILE;
        __syncthreads();   // prior compute done (and W1 staged on first iter)

        // load A tile: row = concat(x[row_idx], edge_attr). 48 float4 per row.
        for (int i = tid; i < E_TILE * 48; i += blockDim.x) {
            int r = i / 48, q = i % 48;
            int e = e0 + r;
            float4 v = make_float4(0.f, 0.f, 0.f, 0.f);
            if (e < E) {
                if (q < 32) {
                    int ri = is64 ? (int)ei64[e] : ei32[e];
                    v = *(const float4*)&x[(size_t)ri * DN + q * 4];
                } else {
                    v = *(const float4*)&ea[(size_t)e * DE + (q - 32) * 4];
                }
            }
            *(float4*)&sA[(size_t)r * KIN + q * 4] = v;
        }
        __syncthreads();

        unsigned long long acc0[E_R], acc1[E_R];
        gemm_rows<KIN, E_R>(sA + (size_t)(wid * E_R) * KIN, sW, c0, acc0, acc1);

        // epilogue: LN + leaky + scatter-add
        int e_base = e0 + wid * E_R;
#pragma unroll
        for (int r = 0; r < E_R; ++r) {
            int e = e_base + r;
            if (e >= E) break;                       // warp-uniform
            float v0, v1, v2, v3;
            unpack2(acc0[r], v0, v1);
            unpack2(acc1[r], v2, v3);
            ln_leaky4(v0, v1, v2, v3, bb, gg, beb);
            int ci = is64 ? (int)ei64[(size_t)E + e] : ei32[E + e];
            float* p = g_sums + (size_t)ci * DN + c0;
            asm volatile("red.global.add.v4.f32 [%0], {%1,%2,%3,%4};"
                         :: "l"(p), "f"(v0), "f"(v1), "f"(v2), "f"(v3) : "memory");
            if (lane == 0) atomicAdd(g_cnt + ci, 1.0f);
        }
    }
}

// ---------------- kernel 3: mean + node MLP + LN + residual ------------------
#define N_R    8
#define N_TILE 64

__global__ void __launch_bounds__(256) node_kernel(
    const float* __restrict__ x, const float* __restrict__ W2,
    const float* __restrict__ b2, const float* __restrict__ g2,
    const float* __restrict__ be2, float* __restrict__ out, int N)
{
    extern __shared__ float smem[];
    float* sW = smem;                    // 128*128 floats (64 KB)
    float* sA = smem + DN * DN;          // 64*128 floats (32 KB)

    int tid  = threadIdx.x;
    int wid  = tid >> 5;
    int lane = tid & 31;
    int c0   = lane * 4;

    for (int i = tid * 4; i < DN * DN; i += blockDim.x * 4)
        *(float4*)&sW[i] = *(const float4*)&W2[i];

    float4 bb  = *(const float4*)&b2[c0];
    float4 gg  = *(const float4*)&g2[c0];
    float4 beb = *(const float4*)&be2[c0];

    int ntiles = (N + N_TILE - 1) / N_TILE;
    for (int t = blockIdx.x; t < ntiles; t += gridDim.x) {
        int n0 = t * N_TILE;
        __syncthreads();

        // load A tile = g_sums / max(cnt, 1)
        for (int i = tid; i < N_TILE * 32; i += blockDim.x) {
            int r = i >> 5, q = i & 31;
            int n = n0 + r;
            float4 v = make_float4(0.f, 0.f, 0.f, 0.f);
            if (n < N) {
                float sc = 1.0f / fmaxf(g_cnt[n], 1.0f);
                v = *(const float4*)&g_sums[(size_t)n * DN + q * 4];
                v.x *= sc; v.y *= sc; v.z *= sc; v.w *= sc;
            }
            *(float4*)&sA[(size_t)r * DN + q * 4] = v;
        }
        __syncthreads();

        unsigned long long acc0[N_R], acc1[N_R];
        gemm_rows<DN, N_R>(sA + (size_t)(wid * N_R) * DN, sW, c0, acc0, acc1);

        int n_base = n0 + wid * N_R;
#pragma unroll
        for (int r = 0; r < N_R; ++r) {
            int n = n_base + r;
            if (n >= N) break;                       // warp-uniform
            float v0, v1, v2, v3;
            unpack2(acc0[r], v0, v1);
            unpack2(acc1[r], v2, v3);
            ln_leaky4(v0, v1, v2, v3, bb, gg, beb);
            float4 xr = *(const float4*)&x[(size_t)n * DN + c0];
            v0 = lrelu(v0 + xr.x);
            v1 = lrelu(v1 + xr.y);
            v2 = lrelu(v2 + xr.z);
            v3 = lrelu(v3 + xr.w);
            *(float4*)&out[(size_t)n * DN + c0] = make_float4(v0, v1, v2, v3);
        }
    }
}

// ---------------- launch ------------------------------------------------------
extern "C" void kernel_launch(void* const* d_in, const int* in_sizes, int n_in,
                              void* d_out, int out_size)
{
    const float* x   = (const float*)d_in[0];
    const void*  ei  = d_in[1];
    const float* ea  = (const float*)d_in[2];
    const float* W1  = (const float*)d_in[3];
    const float* b1  = (const float*)d_in[4];
    const float* g1  = (const float*)d_in[5];
    const float* be1 = (const float*)d_in[6];
    const float* W2  = (const float*)d_in[7];
    const float* b2  = (const float*)d_in[8];
    const float* g2  = (const float*)d_in[9];
    const float* be2 = (const float*)d_in[10];
    float* out = (float*)d_out;

    int N = in_sizes[0] / DN;    // x is (N, 128)
    int E = in_sizes[2] / DE;    // edge_attr is (E, 64)

    size_t smem_edge = (size_t)(KIN * DN + E_TILE * KIN) * sizeof(float); // 192 KB
    size_t smem_node = (size_t)(DN * DN + N_TILE * DN) * sizeof(float);   //  96 KB
    cudaFuncSetAttribute(edge_kernel, cudaFuncAttributeMaxDynamicSharedMemorySize,
                         (int)smem_edge);
    cudaFuncSetAttribute(node_kernel, cudaFuncAttributeMaxDynamicSharedMemorySize,
                         (int)smem_node);

    detect_kernel<<<1, 256>>>((const unsigned*)ei, E);
    zero_kernel<<<512, 256>>>(N);
    edge_kernel<<<148, 256, smem_edge>>>(x, ei, ea, W1, b1, g1, be1, N, E);
    node_kernel<<<296, 256, smem_node>>>(x, W2, b2, g2, be2, out, N);
}

// round 2
// speedup vs baseline: 1.0052x; 1.0052x over previous
#include <cuda_runtime.h>
#include <cstdint>

// ---------------- problem constants (shapes fixed by the dataset) -----------
#define DN   128          // node feature dim / output cols
#define DE   64           // edge feature dim
#define KIN  192          // DN + DE
#define NMAX 50000        // nodes

// ---------------- device scratch (allocation-free) --------------------------
__device__ float g_sums[(size_t)NMAX * DN];   // scatter-sum accumulator
__device__ float g_cnt[NMAX];                 // per-node edge counts
__device__ int   g_is64;                      // edge_index dtype flag

// ---------------- helpers ----------------------------------------------------
__device__ __forceinline__ float lrelu(float v) { return v > 0.f ? v : 0.01f * v; }

// LayerNorm(128) + LeakyReLU on 4 per-lane values; cols of one row live in one warp.
__device__ __forceinline__ void ln_leaky4(float& v0, float& v1, float& v2, float& v3,
                                          float4 bb, float4 gg, float4 beb)
{
    v0 += bb.x; v1 += bb.y; v2 += bb.z; v3 += bb.w;
    float s = v0 + v1 + v2 + v3;
    float q = fmaf(v0, v0, fmaf(v1, v1, fmaf(v2, v2, v3 * v3)));
#pragma unroll
    for (int o = 16; o > 0; o >>= 1) {
        s += __shfl_xor_sync(0xffffffffu, s, o);
        q += __shfl_xor_sync(0xffffffffu, q, o);
    }
    const float inv = 0.0078125f;           // 1/128
    float mean = s * inv;
    float var  = fmaf(q, inv, -mean * mean);
    float rstd = rsqrtf(var + 1e-5f);
    v0 = lrelu(fmaf((v0 - mean) * rstd, gg.x, beb.x));
    v1 = lrelu(fmaf((v1 - mean) * rstd, gg.y, beb.y));
    v2 = lrelu(fmaf((v2 - mean) * rstd, gg.z, beb.z));
    v3 = lrelu(fmaf((v3 - mean) * rstd, gg.w, beb.w));
}

// Packed-f32x2 GEMM core: RR rows per warp, K inner dim, 4 cols/lane (2 f32x2 accs).
// sW is [K][128] row-major in shared; A rows are broadcast reads from shared.
template <int K, int RR>
__device__ __forceinline__ void gemm_rows(const float* __restrict__ arow,
                                          const float* __restrict__ sW,
                                          int c0,
                                          unsigned long long* acc0,
                                          unsigned long long* acc1)
{
#pragma unroll
    for (int r = 0; r < RR; ++r) { acc0[r] = 0ULL; acc1[r] = 0ULL; }

#pragma unroll 2
    for (int k = 0; k < K; k += 2) {
        ulonglong2 b0 = *(const ulonglong2*)(sW + (size_t)(k + 0) * DN + c0);
        ulonglong2 b1 = *(const ulonglong2*)(sW + (size_t)(k + 1) * DN + c0);
#pragma unroll
        for (int r = 0; r < RR; ++r) {
            float2 a = *(const float2*)(arow + (size_t)r * K + k);
            unsigned long long ax, ay;
            asm("mov.b64 %0, {%1, %1};" : "=l"(ax) : "f"(a.x));
            asm("mov.b64 %0, {%1, %1};" : "=l"(ay) : "f"(a.y));
            asm("fma.rn.f32x2 %0, %1, %2, %0;" : "+l"(acc0[r]) : "l"(ax), "l"(b0.x));
            asm("fma.rn.f32x2 %0, %1, %2, %0;" : "+l"(acc1[r]) : "l"(ax), "l"(b0.y));
            asm("fma.rn.f32x2 %0, %1, %2, %0;" : "+l"(acc0[r]) : "l"(ay), "l"(b1.x));
            asm("fma.rn.f32x2 %0, %1, %2, %0;" : "+l"(acc1[r]) : "l"(ay), "l"(b1.y));
        }
    }
}

__device__ __forceinline__ void unpack2(unsigned long long p, float& lo, float& hi)
{
    asm("mov.b64 {%0, %1}, %2;" : "=f"(lo), "=f"(hi) : "l"(p));
}

// ---------------- kernel 0: edge_index dtype detection ----------------------
// int64 little-endian: odd 32-bit words are high halves == 0 (indices < 2^31).
// int32: odd words are real indices, some nonzero with overwhelming probability.
__global__ void detect_kernel(const unsigned* __restrict__ w, int E)
{
    __shared__ unsigned accsh;
    if (threadIdx.x == 0) accsh = 0u;
    __syncthreads();
    int nscan = 4096;
    if (2 * nscan > 2 * E) nscan = E;   // stay within guaranteed buffer (2E words)
    unsigned nz = 0;
    for (int i = threadIdx.x; i < nscan; i += blockDim.x) nz |= w[2 * i + 1];
#pragma unroll
    for (int o = 16; o > 0; o >>= 1) nz |= __shfl_xor_sync(0xffffffffu, nz, o);
    if ((threadIdx.x & 31) == 0) atomicOr(&accsh, nz);
    __syncthreads();
    if (threadIdx.x == 0) g_is64 = (accsh == 0u) ? 1 : 0;
}

// ---------------- kernel 1: zero accumulators --------------------------------
__global__ void zero_kernel(int N)
{
    int tid = blockIdx.x * blockDim.x + threadIdx.x;
    int stride = gridDim.x * blockDim.x;
    float4 z = make_float4(0.f, 0.f, 0.f, 0.f);
    float4* s4 = (float4*)g_sums;
    int n4 = N * (DN / 4);
    for (int i = tid; i < n4; i += stride) s4[i] = z;
    for (int i = tid; i < N; i += stride) g_cnt[i] = 0.f;
}

// ---------------- kernel 2: fused edge MLP + LN + LeakyReLU + scatter --------
// Persistent: grid = 148 (1 block/SM, 192KB smem). Block = 256 threads (8 warps).
// Tile = 128 edges; each warp owns 16 edges, each lane owns 4 output columns.
#define E_R     16
#define E_TILE  128

__global__ void __launch_bounds__(256, 1) edge_kernel(
    const float* __restrict__ x, const void* __restrict__ eidx,
    const float* __restrict__ ea, const float* __restrict__ W1,
    const float* __restrict__ b1, const float* __restrict__ g1,
    const float* __restrict__ be1, int N, int E)
{
    extern __shared__ float smem[];
    float* sW = smem;                    // KIN * DN floats (96 KB)
    float* sA = smem + KIN * DN;         // E_TILE * KIN floats (96 KB)

    int tid  = threadIdx.x;
    int wid  = tid >> 5;
    int lane = tid & 31;
    int c0   = lane * 4;

    // stage W1 once (persistent block)
    for (int i = tid * 4; i < KIN * DN; i += blockDim.x * 4)
        *(float4*)&sW[i] = *(const float4*)&W1[i];

    float4 bb  = *(const float4*)&b1[c0];
    float4 gg  = *(const float4*)&g1[c0];
    float4 beb = *(const float4*)&be1[c0];

    const int is64 = g_is64;
    const long long* ei64 = (const long long*)eidx;
    const int*       ei32 = (const int*)eidx;

    int ntiles = (E + E_TILE - 1) / E_TILE;
    for (int t = blockIdx.x; t < ntiles; t += gridDim.x) {
        int e0 = t * E_TILE;
        __syncthreads();   // prior compute done (and W1 staged on first iter)

        // load A tile: row = concat(x[row_idx], edge_attr). 48 float4 per row.
        for (int i = tid; i < E_TILE * 48; i += blockDim.x) {
            int r = i / 48, q = i % 48;
            int e = e0 + r;
            float4 v = make_float4(0.f, 0.f, 0.f, 0.f);
            if (e < E) {
                if (q < 32) {
                    int ri = is64 ? (int)ei64[e] : ei32[e];
                    v = *(const float4*)&x[(size_t)ri * DN + q * 4];
                } else {
                    v = *(const float4*)&ea[(size_t)e * DE + (q - 32) * 4];
                }
            }
            *(float4*)&sA[(size_t)r * KIN + q * 4] = v;
        }
        __syncthreads();

        unsigned long long acc0[E_R], acc1[E_R];
        gemm_rows<KIN, E_R>(sA + (size_t)(wid * E_R) * KIN, sW, c0, acc0, acc1);

        // epilogue: LN + leaky + scatter-add
        int e_base = e0 + wid * E_R;
#pragma unroll
        for (int r = 0; r < E_R; ++r) {
            int e = e_base + r;
            if (e >= E) break;                       // warp-uniform
            float v0, v1, v2, v3;
            unpack2(acc0[r], v0, v1);
            unpack2(acc1[r], v2, v3);
            ln_leaky4(v0, v1, v2, v3, bb, gg, beb);
            int ci = is64 ? (int)ei64[(size_t)E + e] : ei32[E + e];
            float* p = g_sums + (size_t)ci * DN + c0;
            asm volatile("red.global.add.v4.f32 [%0], {%1,%2,%3,%4};"
                         :: "l"(p), "f"(v0), "f"(v1), "f"(v2), "f"(v3) : "memory");
            if (lane == 0) atomicAdd(g_cnt + ci, 1.0f);
        }
    }
}

// ---------------- kernel 3: mean + node MLP + LN + residual ------------------
#define N_R    8
#define N_TILE 64

__global__ void __launch_bounds__(256) node_kernel(
    const float* __restrict__ x, const float* __restrict__ W2,
    const float* __restrict__ b2, const float* __restrict__ g2,
    const float* __restrict__ be2, float* __restrict__ out, int N)
{
    extern __shared__ float smem[];
    float* sW = smem;                    // 128*128 floats (64 KB)
    float* sA = smem + DN * DN;          // 64*128 floats (32 KB)

    int tid  = threadIdx.x;
    int wid  = tid >> 5;
    int lane = tid & 31;
    int c0   = lane * 4;

    for (int i = tid * 4; i < DN * DN; i += blockDim.x * 4)
        *(float4*)&sW[i] = *(const float4*)&W2[i];

    float4 bb  = *(const float4*)&b2[c0];
    float4 gg  = *(const float4*)&g2[c0];
    float4 beb = *(const float4*)&be2[c0];

    int ntiles = (N + N_TILE - 1) / N_TILE;
    for (int t = blockIdx.x; t < ntiles; t += gridDim.x) {
        int n0 = t * N_TILE;
        __syncthreads();

        // load A tile = g_sums / max(cnt, 1)
        for (int i = tid; i < N_TILE * 32; i += blockDim.x) {
            int r = i >> 5, q = i & 31;
            int n = n0 + r;
            float4 v = make_float4(0.f, 0.f, 0.f, 0.f);
            if (n < N) {
                float sc = 1.0f / fmaxf(g_cnt[n], 1.0f);
                v = *(const float4*)&g_sums[(size_t)n * DN + q * 4];
                v.x *= sc; v.y *= sc; v.z *= sc; v.w *= sc;
            }
            *(float4*)&sA[(size_t)r * DN + q * 4] = v;
        }
        __syncthreads();

        unsigned long long acc0[N_R], acc1[N_R];
        gemm_rows<DN, N_R>(sA + (size_t)(wid * N_R) * DN, sW, c0, acc0, acc1);

        int n_base = n0 + wid * N_R;
#pragma unroll
        for (int r = 0; r < N_R; ++r) {
            int n = n_base + r;
            if (n >= N) break;                       // warp-uniform
            float v0, v1, v2, v3;
            unpack2(acc0[r], v0, v1);
            unpack2(acc1[r], v2, v3);
            ln_leaky4(v0, v1, v2, v3, bb, gg, beb);
            float4 xr = *(const float4*)&x[(size_t)n * DN + c0];
            v0 = lrelu(v0 + xr.x);
            v1 = lrelu(v1 + xr.y);
            v2 = lrelu(v2 + xr.z);
            v3 = lrelu(v3 + xr.w);
            *(float4*)&out[(size_t)n * DN + c0] = make_float4(v0, v1, v2, v3);
        }
    }
}

// ---------------- launch ------------------------------------------------------
extern "C" void kernel_launch(void* const* d_in, const int* in_sizes, int n_in,
                              void* d_out, int out_size)
{
    const float* x   = (const float*)d_in[0];
    const void*  ei  = d_in[1];
    const float* ea  = (const float*)d_in[2];
    const float* W1  = (const float*)d_in[3];
    const float* b1  = (const float*)d_in[4];
    const float* g1  = (const float*)d_in[5];
    const float* be1 = (const float*)d_in[6];
    const float* W2  = (const float*)d_in[7];
    const float* b2  = (const float*)d_in[8];
    const float* g2  = (const float*)d_in[9];
    const float* be2 = (const float*)d_in[10];
    float* out = (float*)d_out;

    int N = in_sizes[0] / DN;    // x is (N, 128)
    int E = in_sizes[2] / DE;    // edge_attr is (E, 64)

    size_t smem_edge = (size_t)(KIN * DN + E_TILE * KIN) * sizeof(float); // 192 KB
    size_t smem_node = (size_t)(DN * DN + N_TILE * DN) * sizeof(float);   //  96 KB
    cudaFuncSetAttribute(edge_kernel, cudaFuncAttributeMaxDynamicSharedMemorySize,
                         (int)smem_edge);
    cudaFuncSetAttribute(node_kernel, cudaFuncAttributeMaxDynamicSharedMemorySize,
                         (int)smem_node);

    detect_kernel<<<1, 256>>>((const unsigned*)ei, E);
    zero_kernel<<<512, 256>>>(N);
    edge_kernel<<<148, 256, smem_edge>>>(x, ei, ea, W1, b1, g1, be1, N, E);
    node_kernel<<<296, 256, smem_node>>>(x, W2, b2, g2, be2, out, N);
}

// round 4
// speedup vs baseline: 1.3606x; 1.3535x over previous
#include <cuda_runtime.h>
#include <cuda_bf16.h>
#include <cstdint>

#define DN   128
#define DE   64
#define NMAX 50000

__device__ float g_sums[(size_t)NMAX * DN];
__device__ float g_cnt[NMAX];
__device__ int   g_is64;

__device__ __forceinline__ float lrelu(float v) { return v > 0.f ? v : 0.01f * v; }

__device__ __forceinline__ uint32_t smem_u32(const void* p) {
    uint32_t a;
    asm("{ .reg .u64 t; cvta.to.shared.u64 t, %1; cvt.u32.u64 %0, t; }" : "=r"(a) : "l"(p));
    return a;
}

__device__ __forceinline__ void ldsm4(uint32_t addr, uint32_t r[4]) {
    asm volatile("ldmatrix.sync.aligned.m8n8.x4.shared.b16 {%0,%1,%2,%3}, [%4];"
                 : "=r"(r[0]), "=r"(r[1]), "=r"(r[2]), "=r"(r[3]) : "r"(addr));
}

__device__ __forceinline__ void mma16816(float c[4], const uint32_t a[4], const uint32_t b[2]) {
    asm volatile("mma.sync.aligned.m16n8k16.row.col.f32.bf16.bf16.f32 "
                 "{%0,%1,%2,%3}, {%4,%5,%6,%7}, {%8,%9}, {%0,%1,%2,%3};"
                 : "+f"(c[0]), "+f"(c[1]), "+f"(c[2]), "+f"(c[3])
                 : "r"(a[0]), "r"(a[1]), "r"(a[2]), "r"(a[3]), "r"(b[0]), "r"(b[1]));
}

// bf16 hi/lo split of a float
__device__ __forceinline__ void split2(float v, unsigned short& h, unsigned short& l) {
    __nv_bfloat16 hb = __float2bfloat16(v);
    __nv_bfloat16 lb = __float2bfloat16(v - __bfloat162float(hb));
    h = *(unsigned short*)&hb;
    l = *(unsigned short*)&lb;
}
// pack 4 floats -> hi pair + lo pair (two b32 each)
__device__ __forceinline__ void split4(float4 v, uint32_t& h01, uint32_t& h23,
                                       uint32_t& l01, uint32_t& l23) {
    __nv_bfloat162 a = __floats2bfloat162_rn(v.x, v.y);
    __nv_bfloat162 b = __floats2bfloat162_rn(v.z, v.w);
    __nv_bfloat162 c = __floats2bfloat162_rn(v.x - __low2float(a), v.y - __high2float(a));
    __nv_bfloat162 d = __floats2bfloat162_rn(v.z - __low2float(b), v.w - __high2float(b));
    h01 = *(uint32_t*)&a; h23 = *(uint32_t*)&b;
    l01 = *(uint32_t*)&c; l23 = *(uint32_t*)&d;
}

// 3-term split GEMM core: warp tile 64x32, KB = row stride bytes, KS = K/16 steps.
// A (M-major rows, K-major cols) and B^T (N rows, K cols) both bf16 swizzled.
template <int KB, int KS>
__device__ __forceinline__ void mma_core(uint32_t aH, uint32_t aL, uint32_t bH, uint32_t bL,
                                         int m0, int n0, int lane, float c[4][4][4])
{
#pragma unroll
    for (int mt = 0; mt < 4; ++mt)
#pragma unroll
        for (int nt = 0; nt < 4; ++nt)
#pragma unroll
            for (int j = 0; j < 4; ++j) c[mt][nt][j] = 0.f;

    uint32_t rA = lane & 15;
    uint32_t kA = (lane >> 4) << 4;
    uint32_t xA = (rA & 7) << 4;
    uint32_t rB = ((lane >> 4) & 1) * 8 + (lane & 7);
    uint32_t kB = ((lane >> 3) & 1) << 4;
    uint32_t xB = (rB & 7) << 4;
    uint32_t aRH = aH + (m0 + rA) * KB;
    uint32_t aRL = aL + (m0 + rA) * KB;
    uint32_t bRH = bH + (n0 + rB) * KB;
    uint32_t bRL = bL + (n0 + rB) * KB;

#pragma unroll 2
    for (int ks = 0; ks < KS; ++ks) {
        uint32_t colA = (((uint32_t)ks * 32) | kA) ^ xA;
        uint32_t colB = (((uint32_t)ks * 32) | kB) ^ xB;
        uint32_t ah[4][4], al[4][4], bh[2][4], bl[2][4];
#pragma unroll
        for (int mt = 0; mt < 4; ++mt) {
            ldsm4(aRH + mt * 16 * KB + colA, ah[mt]);
            ldsm4(aRL + mt * 16 * KB + colA, al[mt]);
        }
#pragma unroll
        for (int p = 0; p < 2; ++p) {
            ldsm4(bRH + p * 16 * KB + colB, bh[p]);
            ldsm4(bRL + p * 16 * KB + colB, bl[p]);
        }
#pragma unroll
        for (int mt = 0; mt < 4; ++mt)
#pragma unroll
            for (int nt = 0; nt < 4; ++nt) {
                const uint32_t* bbh = &bh[nt >> 1][(nt & 1) * 2];
                const uint32_t* bbl = &bl[nt >> 1][(nt & 1) * 2];
                mma16816(c[mt][nt], ah[mt], bbh);
                mma16816(c[mt][nt], al[mt], bbh);
                mma16816(c[mt][nt], ah[mt], bbl);
            }
    }
}

// ---------------- small kernels ------------------------------------------------
__global__ void detect_kernel(const unsigned* __restrict__ w, int E)
{
    __shared__ unsigned accsh;
    if (threadIdx.x == 0) accsh = 0u;
    __syncthreads();
    int nscan = 4096; if (nscan > E) nscan = E;
    unsigned nz = 0;
    for (int i = threadIdx.x; i < nscan; i += blockDim.x) nz |= w[2 * i + 1];
#pragma unroll
    for (int o = 16; o > 0; o >>= 1) nz |= __shfl_xor_sync(0xffffffffu, nz, o);
    if ((threadIdx.x & 31) == 0) atomicOr(&accsh, nz);
    __syncthreads();
    if (threadIdx.x == 0) g_is64 = (accsh == 0u) ? 1 : 0;
}

__global__ void zero_kernel(int N)
{
    int tid = blockIdx.x * blockDim.x + threadIdx.x;
    int stride = gridDim.x * blockDim.x;
    float4 z = make_float4(0.f, 0.f, 0.f, 0.f);
    float4* s4 = (float4*)g_sums;
    int n4 = N * (DN / 4);
    for (int i = tid; i < n4; i += stride) s4[i] = z;
    for (int i = tid; i < N; i += stride) g_cnt[i] = 0.f;
}

// ---------------- edge kernel ---------------------------------------------------
// smem: Bt_h 48K | Bt_l 48K | A_h 48K | A_l 48K | params 1.5K   (C 67.6K overlays A)
#define E_BH 0
#define E_BL 49152
#define E_AH 98304
#define E_AL 147456
#define E_P  196608
#define SMEM_EDGE 198144
#define CSTRIDE 132

__global__ void __launch_bounds__(256, 1) edge_kernel(
    const float* __restrict__ x, const void* __restrict__ eidx,
    const float* __restrict__ ea, const float* __restrict__ W1,
    const float* __restrict__ b1, const float* __restrict__ g1,
    const float* __restrict__ be1, int N, int E)
{
    extern __shared__ char smem[];
    const uint32_t sb = smem_u32(smem);
    float* sC = (float*)(smem + E_AH);
    float* sP = (float*)(smem + E_P);

    int tid = threadIdx.x, wid = tid >> 5, lane = tid & 31;
    int m0 = (wid >> 2) * 64, n0 = (wid & 3) * 32;

    // one-time: W1 (K=192 x N=128) -> Bt[n][k] bf16 hi/lo, swizzled
    for (int i = tid; i < 192 * 32; i += 256) {
        int k = i >> 5, n4 = (i & 31) << 2;
        float4 w = *(const float4*)&W1[(size_t)k * DN + n4];
#pragma unroll
        for (int j = 0; j < 4; ++j) {
            int n = n4 + j;
            unsigned short h, l;
            split2((&w.x)[j], h, l);
            uint32_t a = sb + E_BH + n * 384 + (((uint32_t)(2 * k)) ^ (((uint32_t)(n & 7)) << 4));
            asm volatile("st.shared.b16 [%0], %1;" :: "r"(a), "h"(h));
            asm volatile("st.shared.b16 [%0], %1;" :: "r"(a + (E_BL - E_BH)), "h"(l));
        }
    }
    for (int i = tid; i < DN; i += 256) { sP[i] = b1[i]; sP[DN + i] = g1[i]; sP[2 * DN + i] = be1[i]; }

    const int is64 = g_is64;
    const long long* ei64 = (const long long*)eidx;
    const int*       ei32 = (const int*)eidx;

    int ntiles = (E + 127) >> 7;
    for (int t = blockIdx.x; t < ntiles; t += gridDim.x) {
        int e0 = t << 7;
        __syncthreads();                       // prev C reads done / W staged

        // gather + bf16-split A tile (128 x 192)
        for (int i = tid; i < 128 * 48; i += 256) {
            int r = i / 48, q = i - r * 48;
            int e = e0 + r;
            float4 v = make_float4(0.f, 0.f, 0.f, 0.f);
            if (e < E) {
                if (q < 32) {
                    int ri = is64 ? (int)ei64[e] : ei32[e];
                    v = *(const float4*)&x[(size_t)ri * DN + q * 4];
                } else {
                    v = *(const float4*)&ea[(size_t)e * DE + (q - 32) * 4];
                }
            }
            uint32_t h01, h23, l01, l23;
            split4(v, h01, h23, l01, l23);
            uint32_t col = ((uint32_t)(8 * q)) ^ (((uint32_t)(r & 7)) << 4);
            uint32_t a = sb + E_AH + r * 384 + col;
            asm volatile("st.shared.v2.b32 [%0], {%1,%2};" :: "r"(a), "r"(h01), "r"(h23));
            asm volatile("st.shared.v2.b32 [%0], {%1,%2};" :: "r"(a + (E_AL - E_AH)), "r"(l01), "r"(l23));
        }
        __syncthreads();

        float c[4][4][4];
        mma_core<384, 12>(sb + E_AH, sb + E_AL, sb + E_BH, sb + E_BL, m0, n0, lane, c);
        __syncthreads();                       // all A reads done before C overwrite

        int rlo = lane >> 2, cp = (lane & 3) * 2;
#pragma unroll
        for (int mt = 0; mt < 4; ++mt)
#pragma unroll
            for (int nt = 0; nt < 4; ++nt) {
                int row = m0 + mt * 16 + rlo, col = n0 + nt * 8 + cp;
                *(float2*)&sC[row * CSTRIDE + col]       = make_float2(c[mt][nt][0], c[mt][nt][1]);
                *(float2*)&sC[(row + 8) * CSTRIDE + col] = make_float2(c[mt][nt][2], c[mt][nt][3]);
            }
        __syncthreads();

        // LN + leaky + scatter; warp owns rows [16*wid, 16*wid+16)
        int c0 = lane * 4;
        float4 bb  = *(const float4*)&sP[c0];
        float4 gg  = *(const float4*)&sP[DN + c0];
        float4 beb = *(const float4*)&sP[2 * DN + c0];
        for (int j = 0; j < 16; ++j) {
            int r = wid * 16 + j;
            int e = e0 + r;
            float4 v = *(const float4*)&sC[r * CSTRIDE + c0];
            float v0 = v.x + bb.x, v1 = v.y + bb.y, v2 = v.z + bb.z, v3 = v.w + bb.w;
            float s = v0 + v1 + v2 + v3;
            float q = fmaf(v0, v0, fmaf(v1, v1, fmaf(v2, v2, v3 * v3)));
#pragma unroll
            for (int o = 16; o > 0; o >>= 1) {
                s += __shfl_xor_sync(0xffffffffu, s, o);
                q += __shfl_xor_sync(0xffffffffu, q, o);
            }
            const float inv = 0.0078125f;
            float mean = s * inv;
            float var  = fmaf(q, inv, -mean * mean);
            float rstd = rsqrtf(var + 1e-5f);
            float o0 = lrelu(fmaf((v0 - mean) * rstd, gg.x, beb.x));
            float o1 = lrelu(fmaf((v1 - mean) * rstd, gg.y, beb.y));
            float o2 = lrelu(fmaf((v2 - mean) * rstd, gg.z, beb.z));
            float o3 = lrelu(fmaf((v3 - mean) * rstd, gg.w, beb.w));
            if (e < E) {
                int ci = is64 ? (int)ei64[(size_t)E + e] : ei32[E + e];
                float* p = g_sums + (size_t)ci * DN + c0;
                asm volatile("red.global.add.v4.f32 [%0], {%1,%2,%3,%4};"
                             :: "l"(p), "f"(o0), "f"(o1), "f"(o2), "f"(o3) : "memory");
                if (lane == 0) atomicAdd(g_cnt + ci, 1.0f);
            }
        }
    }
}

// ---------------- node kernel ----------------------------------------------------
// smem: Bt_h 32K | Bt_l 32K | A_h 32K | A_l 32K (C 67.6K overlays A+) | params
#define N_BH 0
#define N_BL 32768
#define N_AH 65536
#define N_AL 98304
#define N_P  133120
#define SMEM_NODE 134656

__global__ void __launch_bounds__(256, 1) node_kernel(
    const float* __restrict__ x, const float* __restrict__ W2,
    const float* __restrict__ b2, const float* __restrict__ g2,
    const float* __restrict__ be2, float* __restrict__ out, int N)
{
    extern __shared__ char smem[];
    const uint32_t sb = smem_u32(smem);
    float* sC = (float*)(smem + N_AH);
    float* sP = (float*)(smem + N_P);

    int tid = threadIdx.x, wid = tid >> 5, lane = tid & 31;
    int m0 = (wid >> 2) * 64, n0 = (wid & 3) * 32;

    for (int i = tid; i < 128 * 32; i += 256) {
        int k = i >> 5, n4 = (i & 31) << 2;
        float4 w = *(const float4*)&W2[(size_t)k * DN + n4];
#pragma unroll
        for (int j = 0; j < 4; ++j) {
            int n = n4 + j;
            unsigned short h, l;
            split2((&w.x)[j], h, l);
            uint32_t a = sb + N_BH + n * 256 + (((uint32_t)(2 * k)) ^ (((uint32_t)(n & 7)) << 4));
            asm volatile("st.shared.b16 [%0], %1;" :: "r"(a), "h"(h));
            asm volatile("st.shared.b16 [%0], %1;" :: "r"(a + (N_BL - N_BH)), "h"(l));
        }
    }
    for (int i = tid; i < DN; i += 256) { sP[i] = b2[i]; sP[DN + i] = g2[i]; sP[2 * DN + i] = be2[i]; }

    int ntiles = (N + 127) >> 7;
    for (int t = blockIdx.x; t < ntiles; t += gridDim.x) {
        int nb = t << 7;
        __syncthreads();

        for (int i = tid; i < 128 * 32; i += 256) {
            int r = i >> 5, q = i & 31;
            int n = nb + r;
            float4 v = make_float4(0.f, 0.f, 0.f, 0.f);
            if (n < N) {
                float sc = 1.0f / fmaxf(g_cnt[n], 1.0f);
                v = *(const float4*)&g_sums[(size_t)n * DN + q * 4];
                v.x *= sc; v.y *= sc; v.z *= sc; v.w *= sc;
            }
            uint32_t h01, h23, l01, l23;
            split4(v, h01, h23, l01, l23);
            uint32_t col = ((uint32_t)(8 * q)) ^ (((uint32_t)(r & 7)) << 4);
            uint32_t a = sb + N_AH + r * 256 + col;
            asm volatile("st.shared.v2.b32 [%0], {%1,%2};" :: "r"(a), "r"(h01), "r"(h23));
            asm volatile("st.shared.v2.b32 [%0], {%1,%2};" :: "r"(a + (N_AL - N_AH)), "r"(l01), "r"(l23));
        }
        __syncthreads();

        float c[4][4][4];
        mma_core<256, 8>(sb + N_AH, sb + N_AL, sb + N_BH, sb + N_BL, m0, n0, lane, c);
        __syncthreads();

        int rlo = lane >> 2, cp = (lane & 3) * 2;
#pragma unroll
        for (int mt = 0; mt < 4; ++mt)
#pragma unroll
            for (int nt = 0; nt < 4; ++nt) {
                int row = m0 + mt * 16 + rlo, col = n0 + nt * 8 + cp;
                *(float2*)&sC[row * CSTRIDE + col]       = make_float2(c[mt][nt][0], c[mt][nt][1]);
                *(float2*)&sC[(row + 8) * CSTRIDE + col] = make_float2(c[mt][nt][2], c[mt][nt][3]);
            }
        __syncthreads();

        int c0 = lane * 4;
        float4 bb  = *(const float4*)&sP[c0];
        float4 gg  = *(const float4*)&sP[DN + c0];
        float4 beb = *(const float4*)&sP[2 * DN + c0];
        for (int j = 0; j < 16; ++j) {
            int r = wid * 16 + j;
            int n = nb + r;
            float4 v = *(const float4*)&sC[r * CSTRIDE + c0];
            float v0 = v.x + bb.x, v1 = v.y + bb.y, v2 = v.z + bb.z, v3 = v.w + bb.w;
            float s = v0 + v1 + v2 + v3;
            float q = fmaf(v0, v0, fmaf(v1, v1, fmaf(v2, v2, v3 * v3)));
#pragma unroll
            for (int o = 16; o > 0; o >>= 1) {
                s += __shfl_xor_sync(0xffffffffu, s, o);
                q += __shfl_xor_sync(0xffffffffu, q, o);
            }
            const float inv = 0.0078125f;
            float mean = s * inv;
            float var  = fmaf(q, inv, -mean * mean);
            float rstd = rsqrtf(var + 1e-5f);
            float o0 = lrelu(fmaf((v0 - mean) * rstd, gg.x, beb.x));
            float o1 = lrelu(fmaf((v1 - mean) * rstd, gg.y, beb.y));
            float o2 = lrelu(fmaf((v2 - mean) * rstd, gg.z, beb.z));
            float o3 = lrelu(fmaf((v3 - mean) * rstd, gg.w, beb.w));
            if (n < N) {
                float4 xr = *(const float4*)&x[(size_t)n * DN + c0];
                o0 = lrelu(o0 + xr.x);
                o1 = lrelu(o1 + xr.y);
                o2 = lrelu(o2 + xr.z);
                o3 = lrelu(o3 + xr.w);
                *(float4*)&out[(size_t)n * DN + c0] = make_float4(o0, o1, o2, o3);
            }
        }
    }
}

// ---------------- launch ----------------------------------------------------------
extern "C" void kernel_launch(void* const* d_in, const int* in_sizes, int n_in,
                              void* d_out, int out_size)
{
    const float* x   = (const float*)d_in[0];
    const void*  ei  = d_in[1];
    const float* ea  = (const float*)d_in[2];
    const float* W1  = (const float*)d_in[3];
    const float* b1  = (const float*)d_in[4];
    const float* g1  = (const float*)d_in[5];
    const float* be1 = (const float*)d_in[6];
    const float* W2  = (const float*)d_in[7];
    const float* b2  = (const float*)d_in[8];
    const float* g2  = (const float*)d_in[9];
    const float* be2 = (const float*)d_in[10];
    float* out = (float*)d_out;

    int N = in_sizes[0] / DN;
    int E = in_sizes[2] / DE;

    cudaFuncSetAttribute(edge_kernel, cudaFuncAttributeMaxDynamicSharedMemorySize, SMEM_EDGE);
    cudaFuncSetAttribute(node_kernel, cudaFuncAttributeMaxDynamicSharedMemorySize, SMEM_NODE);

    detect_kernel<<<1, 256>>>((const unsigned*)ei, E);
    zero_kernel<<<512, 256>>>(N);
    edge_kernel<<<148, 256, SMEM_EDGE>>>(x, ei, ea, W1, b1, g1, be1, N, E);
    node_kernel<<<148, 256, SMEM_NODE>>>(x, W2, b2, g2, be2, out, N);
}

// round 5
// speedup vs baseline: 1.7260x; 1.2686x over previous
#include <cuda_runtime.h>
#include <cuda_bf16.h>
#include <cstdint>

#define DN   128
#define DE   64
#define NMAX 50000

__device__ float g_sums[(size_t)NMAX * DN];
__device__ float g_cnt[NMAX];
__device__ int   g_is64;

__device__ __forceinline__ float lrelu(float v) { return v > 0.f ? v : 0.01f * v; }

__device__ __forceinline__ uint32_t smem_u32(const void* p) {
    uint32_t a;
    asm("{ .reg .u64 t; cvta.to.shared.u64 t, %1; cvt.u32.u64 %0, t; }" : "=r"(a) : "l"(p));
    return a;
}

__device__ __forceinline__ void ldsm4(uint32_t addr, uint32_t r[4]) {
    asm volatile("ldmatrix.sync.aligned.m8n8.x4.shared.b16 {%0,%1,%2,%3}, [%4];"
                 : "=r"(r[0]), "=r"(r[1]), "=r"(r[2]), "=r"(r[3]) : "r"(addr));
}

__device__ __forceinline__ void mma16816(float c[4], const uint32_t a[4], const uint32_t b[2]) {
    asm volatile("mma.sync.aligned.m16n8k16.row.col.f32.bf16.bf16.f32 "
                 "{%0,%1,%2,%3}, {%4,%5,%6,%7}, {%8,%9}, {%0,%1,%2,%3};"
                 : "+f"(c[0]), "+f"(c[1]), "+f"(c[2]), "+f"(c[3])
                 : "r"(a[0]), "r"(a[1]), "r"(a[2]), "r"(a[3]), "r"(b[0]), "r"(b[1]));
}

__device__ __forceinline__ void split2(float v, unsigned short& h, unsigned short& l) {
    __nv_bfloat16 hb = __float2bfloat16(v);
    __nv_bfloat16 lb = __float2bfloat16(v - __bfloat162float(hb));
    h = *(unsigned short*)&hb;
    l = *(unsigned short*)&lb;
}
__device__ __forceinline__ void split4(float4 v, uint32_t& h01, uint32_t& h23,
                                       uint32_t& l01, uint32_t& l23) {
    __nv_bfloat162 a = __floats2bfloat162_rn(v.x, v.y);
    __nv_bfloat162 b = __floats2bfloat162_rn(v.z, v.w);
    __nv_bfloat162 c = __floats2bfloat162_rn(v.x - __low2float(a), v.y - __high2float(a));
    __nv_bfloat162 d = __floats2bfloat162_rn(v.z - __low2float(b), v.w - __high2float(b));
    h01 = *(uint32_t*)&a; h23 = *(uint32_t*)&b;
    l01 = *(uint32_t*)&c; l23 = *(uint32_t*)&d;
}

// 3-term split GEMM core. Warp tile (MT*16) x 32. KB = row stride bytes, KS = K/16.
template <int KB, int KS, int MT>
__device__ __forceinline__ void mma_core(uint32_t aH, uint32_t aL, uint32_t bH, uint32_t bL,
                                         int m0, int n0, int lane, float (*c)[4][4])
{
#pragma unroll
    for (int mt = 0; mt < MT; ++mt)
#pragma unroll
        for (int nt = 0; nt < 4; ++nt)
#pragma unroll
            for (int j = 0; j < 4; ++j) c[mt][nt][j] = 0.f;

    uint32_t rA = lane & 15;
    uint32_t kA = (lane >> 4) << 4;
    uint32_t xA = (rA & 7) << 4;
    uint32_t rB = ((lane >> 4) & 1) * 8 + (lane & 7);
    uint32_t kB = ((lane >> 3) & 1) << 4;
    uint32_t xB = (rB & 7) << 4;
    uint32_t aRH = aH + (m0 + rA) * KB;
    uint32_t aRL = aL + (m0 + rA) * KB;
    uint32_t bRH = bH + (n0 + rB) * KB;
    uint32_t bRL = bL + (n0 + rB) * KB;

#pragma unroll 2
    for (int ks = 0; ks < KS; ++ks) {
        uint32_t colA = (((uint32_t)ks * 32) | kA) ^ xA;
        uint32_t colB = (((uint32_t)ks * 32) | kB) ^ xB;
        uint32_t ah[MT][4], al[MT][4], bh[2][4], bl[2][4];
#pragma unroll
        for (int mt = 0; mt < MT; ++mt) {
            ldsm4(aRH + mt * 16 * KB + colA, ah[mt]);
            ldsm4(aRL + mt * 16 * KB + colA, al[mt]);
        }
#pragma unroll
        for (int p = 0; p < 2; ++p) {
            ldsm4(bRH + p * 16 * KB + colB, bh[p]);
            ldsm4(bRL + p * 16 * KB + colB, bl[p]);
        }
#pragma unroll
        for (int mt = 0; mt < MT; ++mt)
#pragma unroll
            for (int nt = 0; nt < 4; ++nt) {
                const uint32_t* bbh = &bh[nt >> 1][(nt & 1) * 2];
                const uint32_t* bbl = &bl[nt >> 1][(nt & 1) * 2];
                mma16816(c[mt][nt], ah[mt], bbh);
                mma16816(c[mt][nt], al[mt], bbh);
                mma16816(c[mt][nt], ah[mt], bbl);
            }
    }
}

// ---------------- small kernels -------------------------------------------------
__global__ void detect_kernel(const unsigned* __restrict__ w, int E)
{
    __shared__ unsigned accsh;
    if (threadIdx.x == 0) accsh = 0u;
    __syncthreads();
    int nscan = 4096; if (nscan > E) nscan = E;
    unsigned nz = 0;
    for (int i = threadIdx.x; i < nscan; i += blockDim.x) nz |= w[2 * i + 1];
#pragma unroll
    for (int o = 16; o > 0; o >>= 1) nz |= __shfl_xor_sync(0xffffffffu, nz, o);
    if ((threadIdx.x & 31) == 0) atomicOr(&accsh, nz);
    __syncthreads();
    if (threadIdx.x == 0) g_is64 = (accsh == 0u) ? 1 : 0;
}

__global__ void zero_kernel(int N)
{
    int tid = blockIdx.x * blockDim.x + threadIdx.x;
    int stride = gridDim.x * blockDim.x;
    float4 z = make_float4(0.f, 0.f, 0.f, 0.f);
    float4* s4 = (float4*)g_sums;
    int n4 = N * (DN / 4);
    for (int i = tid; i < n4; i += stride) s4[i] = z;
    for (int i = tid; i < N; i += stride) g_cnt[i] = 0.f;
}

// ---------------- edge kernel: 64-edge tiles, register-prefetch pipeline --------
// smem: Bt_h 48K | Bt_l 48K | A_h 24K | A_l 24K (C 33.8K overlays A) | params
#define E_BH 0
#define E_BL 49152
#define E_A  98304
#define E_AL 122880
#define E_P  147456
#define SMEM_EDGE 148992
#define CSTRIDE 132

__global__ void __launch_bounds__(256, 1) edge_kernel(
    const float* __restrict__ x, const void* __restrict__ eidx,
    const float* __restrict__ ea, const float* __restrict__ W1,
    const float* __restrict__ b1, const float* __restrict__ g1,
    const float* __restrict__ be1, int N, int E)
{
    extern __shared__ char smem[];
    const uint32_t sb = smem_u32(smem);
    float* sC = (float*)(smem + E_A);
    float* sP = (float*)(smem + E_P);

    int tid = threadIdx.x, wid = tid >> 5, lane = tid & 31;
    int m0 = (wid >> 2) * 32, n0 = (wid & 3) * 32;

    // one-time: W1 (192 x 128) -> Bt[n][k] bf16 hi/lo, swizzled (row stride 384B)
    for (int i = tid; i < 192 * 32; i += 256) {
        int k = i >> 5, n4 = (i & 31) << 2;
        float4 w = *(const float4*)&W1[(size_t)k * DN + n4];
#pragma unroll
        for (int j = 0; j < 4; ++j) {
            int n = n4 + j;
            unsigned short h, l;
            split2((&w.x)[j], h, l);
            uint32_t a = sb + E_BH + n * 384 + (((uint32_t)(2 * k)) ^ (((uint32_t)(n & 7)) << 4));
            asm volatile("st.shared.b16 [%0], %1;" :: "r"(a), "h"(h));
            asm volatile("st.shared.b16 [%0], %1;" :: "r"(a + (E_BL - E_BH)), "h"(l));
        }
    }
    for (int i = tid; i < DN; i += 256) { sP[i] = b1[i]; sP[DN + i] = g1[i]; sP[2 * DN + i] = be1[i]; }

    const int is64 = g_is64;
    const long long* ei64 = (const long long*)eidx;
    const int*       ei32 = (const int*)eidx;

    int ntiles = (E + 63) >> 6;
    float4 v[12];

    // prologue: gather + convert tile t0
    int t = blockIdx.x;
    {
        int e0 = t << 6;
#pragma unroll
        for (int j = 0; j < 12; ++j) {
            int i = tid + (j << 8);
            int r = i / 48, q = i - r * 48;
            int e = e0 + r;
            float4 val = make_float4(0.f, 0.f, 0.f, 0.f);
            if (e < E) {
                if (q < 32) {
                    int ri = is64 ? (int)ei64[e] : ei32[e];
                    val = *(const float4*)&x[(size_t)ri * DN + q * 4];
                } else val = *(const float4*)&ea[(size_t)e * DE + (q - 32) * 4];
            }
            v[j] = val;
        }
#pragma unroll
        for (int j = 0; j < 12; ++j) {
            int i = tid + (j << 8);
            int r = i / 48, q = i - r * 48;
            uint32_t h01, h23, l01, l23;
            split4(v[j], h01, h23, l01, l23);
            uint32_t a = sb + E_A + r * 384 + (((uint32_t)(8 * q)) ^ (((uint32_t)(r & 7)) << 4));
            asm volatile("st.shared.v2.b32 [%0], {%1,%2};" :: "r"(a), "r"(h01), "r"(h23));
            asm volatile("st.shared.v2.b32 [%0], {%1,%2};" :: "r"(a + (E_AL - E_A)), "r"(l01), "r"(l23));
        }
    }
    __syncthreads();

    for (; t < ntiles; t += gridDim.x) {
        int tn = t + gridDim.x;
        // prefetch tile tn into registers (latency hides under mma)
        if (tn < ntiles) {
            int e0 = tn << 6;
#pragma unroll
            for (int j = 0; j < 12; ++j) {
                int i = tid + (j << 8);
                int r = i / 48, q = i - r * 48;
                int e = e0 + r;
                float4 val = make_float4(0.f, 0.f, 0.f, 0.f);
                if (e < E) {
                    if (q < 32) {
                        int ri = is64 ? (int)ei64[e] : ei32[e];
                        val = *(const float4*)&x[(size_t)ri * DN + q * 4];
                    } else val = *(const float4*)&ea[(size_t)e * DE + (q - 32) * 4];
                }
                v[j] = val;
            }
        }

        float c[2][4][4];
        mma_core<384, 12, 2>(sb + E_A, sb + E_AL, sb + E_BH, sb + E_BL, m0, n0, lane, c);
        __syncthreads();                         // all A reads done

        int rlo = lane >> 2, cp = (lane & 3) * 2;
#pragma unroll
        for (int mt = 0; mt < 2; ++mt)
#pragma unroll
            for (int nt = 0; nt < 4; ++nt) {
                int row = m0 + mt * 16 + rlo, col = n0 + nt * 8 + cp;
                *(float2*)&sC[row * CSTRIDE + col]       = make_float2(c[mt][nt][0], c[mt][nt][1]);
                *(float2*)&sC[(row + 8) * CSTRIDE + col] = make_float2(c[mt][nt][2], c[mt][nt][3]);
            }
        __syncthreads();

        // epilogue: warp owns rows [8*wid, 8*wid+8)
        {
            int e0 = t << 6;
            int c0 = lane * 4;
            float4 bb  = *(const float4*)&sP[c0];
            float4 gg  = *(const float4*)&sP[DN + c0];
            float4 beb = *(const float4*)&sP[2 * DN + c0];
#pragma unroll
            for (int j = 0; j < 8; ++j) {
                int r = wid * 8 + j;
                int e = e0 + r;
                float4 cv = *(const float4*)&sC[r * CSTRIDE + c0];
                float v0 = cv.x + bb.x, v1 = cv.y + bb.y, v2 = cv.z + bb.z, v3 = cv.w + bb.w;
                float s = v0 + v1 + v2 + v3;
                float q = fmaf(v0, v0, fmaf(v1, v1, fmaf(v2, v2, v3 * v3)));
#pragma unroll
                for (int o = 16; o > 0; o >>= 1) {
                    s += __shfl_xor_sync(0xffffffffu, s, o);
                    q += __shfl_xor_sync(0xffffffffu, q, o);
                }
                const float inv = 0.0078125f;
                float mean = s * inv;
                float var  = fmaf(q, inv, -mean * mean);
                float rstd = rsqrtf(var + 1e-5f);
                float o0 = lrelu(fmaf((v0 - mean) * rstd, gg.x, beb.x));
                float o1 = lrelu(fmaf((v1 - mean) * rstd, gg.y, beb.y));
                float o2 = lrelu(fmaf((v2 - mean) * rstd, gg.z, beb.z));
                float o3 = lrelu(fmaf((v3 - mean) * rstd, gg.w, beb.w));
                if (e < E) {
                    int ci = is64 ? (int)ei64[(size_t)E + e] : ei32[E + e];
                    float* p = g_sums + (size_t)ci * DN + c0;
                    asm volatile("red.global.add.v4.f32 [%0], {%1,%2,%3,%4};"
                                 :: "l"(p), "f"(o0), "f"(o1), "f"(o2), "f"(o3) : "memory");
                    if (lane == 0) atomicAdd(g_cnt + ci, 1.0f);
                }
            }
        }
        __syncthreads();                         // C reads done before A overwrite

        if (tn < ntiles) {
#pragma unroll
            for (int j = 0; j < 12; ++j) {
                int i = tid + (j << 8);
                int r = i / 48, q = i - r * 48;
                uint32_t h01, h23, l01, l23;
                split4(v[j], h01, h23, l01, l23);
                uint32_t a = sb + E_A + r * 384 + (((uint32_t)(8 * q)) ^ (((uint32_t)(r & 7)) << 4));
                asm volatile("st.shared.v2.b32 [%0], {%1,%2};" :: "r"(a), "r"(h01), "r"(h23));
                asm volatile("st.shared.v2.b32 [%0], {%1,%2};" :: "r"(a + (E_AL - E_A)), "r"(l01), "r"(l23));
            }
        }
        __syncthreads();                         // A ready for next mma
    }
}

// ---------------- node kernel: 64-row tiles, same pipeline ----------------------
#define N_BH 0
#define N_BL 32768
#define N_A  65536
#define N_AL 81920
#define N_P  100352
#define SMEM_NODE 101888

__global__ void __launch_bounds__(256, 1) node_kernel(
    const float* __restrict__ x, const float* __restrict__ W2,
    const float* __restrict__ b2, const float* __restrict__ g2,
    const float* __restrict__ be2, float* __restrict__ out, int N)
{
    extern __shared__ char smem[];
    const uint32_t sb = smem_u32(smem);
    float* sC = (float*)(smem + N_A);
    float* sP = (float*)(smem + N_P);

    int tid = threadIdx.x, wid = tid >> 5, lane = tid & 31;
    int m0 = (wid >> 2) * 32, n0 = (wid & 3) * 32;

    for (int i = tid; i < 128 * 32; i += 256) {
        int k = i >> 5, n4 = (i & 31) << 2;
        float4 w = *(const float4*)&W2[(size_t)k * DN + n4];
#pragma unroll
        for (int j = 0; j < 4; ++j) {
            int n = n4 + j;
            unsigned short h, l;
            split2((&w.x)[j], h, l);
            uint32_t a = sb + N_BH + n * 256 + (((uint32_t)(2 * k)) ^ (((uint32_t)(n & 7)) << 4));
            asm volatile("st.shared.b16 [%0], %1;" :: "r"(a), "h"(h));
            asm volatile("st.shared.b16 [%0], %1;" :: "r"(a + (N_BL - N_BH)), "h"(l));
        }
    }
    for (int i = tid; i < DN; i += 256) { sP[i] = b2[i]; sP[DN + i] = g2[i]; sP[2 * DN + i] = be2[i]; }

    int ntiles = (N + 63) >> 6;
    float4 v[8];

    int t = blockIdx.x;
    {
        int nb = t << 6;
#pragma unroll
        for (int j = 0; j < 8; ++j) {
            int i = tid + (j << 8);
            int r = i >> 5, q = i & 31;
            int n = nb + r;
            float4 val = make_float4(0.f, 0.f, 0.f, 0.f);
            if (n < N) {
                float sc = 1.0f / fmaxf(g_cnt[n], 1.0f);
                val = *(const float4*)&g_sums[(size_t)n * DN + q * 4];
                val.x *= sc; val.y *= sc; val.z *= sc; val.w *= sc;
            }
            v[j] = val;
        }
#pragma unroll
        for (int j = 0; j < 8; ++j) {
            int i = tid + (j << 8);
            int r = i >> 5, q = i & 31;
            uint32_t h01, h23, l01, l23;
            split4(v[j], h01, h23, l01, l23);
            uint32_t a = sb + N_A + r * 256 + (((uint32_t)(8 * q)) ^ (((uint32_t)(r & 7)) << 4));
            asm volatile("st.shared.v2.b32 [%0], {%1,%2};" :: "r"(a), "r"(h01), "r"(h23));
            asm volatile("st.shared.v2.b32 [%0], {%1,%2};" :: "r"(a + (N_AL - N_A)), "r"(l01), "r"(l23));
        }
    }
    __syncthreads();

    for (; t < ntiles; t += gridDim.x) {
        int tn = t + gridDim.x;
        if (tn < ntiles) {
            int nb = tn << 6;
#pragma unroll
            for (int j = 0; j < 8; ++j) {
                int i = tid + (j << 8);
                int r = i >> 5, q = i & 31;
                int n = nb + r;
                float4 val = make_float4(0.f, 0.f, 0.f, 0.f);
                if (n < N) {
                    float sc = 1.0f / fmaxf(g_cnt[n], 1.0f);
                    val = *(const float4*)&g_sums[(size_t)n * DN + q * 4];
                    val.x *= sc; val.y *= sc; val.z *= sc; val.w *= sc;
                }
                v[j] = val;
            }
        }

        float c[2][4][4];
        mma_core<256, 8, 2>(sb + N_A, sb + N_AL, sb + N_BH, sb + N_BL, m0, n0, lane, c);
        __syncthreads();

        int rlo = lane >> 2, cp = (lane & 3) * 2;
#pragma unroll
        for (int mt = 0; mt < 2; ++mt)
#pragma unroll
            for (int nt = 0; nt < 4; ++nt) {
                int row = m0 + mt * 16 + rlo, col = n0 + nt * 8 + cp;
                *(float2*)&sC[row * CSTRIDE + col]       = make_float2(c[mt][nt][0], c[mt][nt][1]);
                *(float2*)&sC[(row + 8) * CSTRIDE + col] = make_float2(c[mt][nt][2], c[mt][nt][3]);
            }
        __syncthreads();

        {
            int nb = t << 6;
            int c0 = lane * 4;
            float4 bb  = *(const float4*)&sP[c0];
            float4 gg  = *(const float4*)&sP[DN + c0];
            float4 beb = *(const float4*)&sP[2 * DN + c0];
#pragma unroll
            for (int j = 0; j < 8; ++j) {
                int r = wid * 8 + j;
                int n = nb + r;
                float4 cv = *(const float4*)&sC[r * CSTRIDE + c0];
                float v0 = cv.x + bb.x, v1 = cv.y + bb.y, v2 = cv.z + bb.z, v3 = cv.w + bb.w;
                float s = v0 + v1 + v2 + v3;
                float q = fmaf(v0, v0, fmaf(v1, v1, fmaf(v2, v2, v3 * v3)));
#pragma unroll
                for (int o = 16; o > 0; o >>= 1) {
                    s += __shfl_xor_sync(0xffffffffu, s, o);
                    q += __shfl_xor_sync(0xffffffffu, q, o);
                }
                const float inv = 0.0078125f;
                float mean = s * inv;
                float var  = fmaf(q, inv, -mean * mean);
                float rstd = rsqrtf(var + 1e-5f);
                float o0 = lrelu(fmaf((v0 - mean) * rstd, gg.x, beb.x));
                float o1 = lrelu(fmaf((v1 - mean) * rstd, gg.y, beb.y));
                float o2 = lrelu(fmaf((v2 - mean) * rstd, gg.z, beb.z));
                float o3 = lrelu(fmaf((v3 - mean) * rstd, gg.w, beb.w));
                if (n < N) {
                    float4 xr = *(const float4*)&x[(size_t)n * DN + c0];
                    o0 = lrelu(o0 + xr.x);
                    o1 = lrelu(o1 + xr.y);
                    o2 = lrelu(o2 + xr.z);
                    o3 = lrelu(o3 + xr.w);
                    *(float4*)&out[(size_t)n * DN + c0] = make_float4(o0, o1, o2, o3);
                }
            }
        }
        __syncthreads();

        if (tn < ntiles) {
#pragma unroll
            for (int j = 0; j < 8; ++j) {
                int i = tid + (j << 8);
                int r = i >> 5, q = i & 31;
                uint32_t h01, h23, l01, l23;
                split4(v[j], h01, h23, l01, l23);
                uint32_t a = sb + N_A + r * 256 + (((uint32_t)(8 * q)) ^ (((uint32_t)(r & 7)) << 4));
                asm volatile("st.shared.v2.b32 [%0], {%1,%2};" :: "r"(a), "r"(h01), "r"(h23));
                asm volatile("st.shared.v2.b32 [%0], {%1,%2};" :: "r"(a + (N_AL - N_A)), "r"(l01), "r"(l23));
            }
        }
        __syncthreads();
    }
}

// ---------------- launch ----------------------------------------------------------
extern "C" void kernel_launch(void* const* d_in, const int* in_sizes, int n_in,
                              void* d_out, int out_size)
{
    const float* x   = (const float*)d_in[0];
    const void*  ei  = d_in[1];
    const float* ea  = (const float*)d_in[2];
    const float* W1  = (const float*)d_in[3];
    const float* b1  = (const float*)d_in[4];
    const float* g1  = (const float*)d_in[5];
    const float* be1 = (const float*)d_in[6];
    const float* W2  = (const float*)d_in[7];
    const float* b2  = (const float*)d_in[8];
    const float* g2  = (const float*)d_in[9];
    const float* be2 = (const float*)d_in[10];
    float* out = (float*)d_out;

    int N = in_sizes[0] / DN;
    int E = in_sizes[2] / DE;

    cudaFuncSetAttribute(edge_kernel, cudaFuncAttributeMaxDynamicSharedMemorySize, SMEM_EDGE);
    cudaFuncSetAttribute(node_kernel, cudaFuncAttributeMaxDynamicSharedMemorySize, SMEM_NODE);

    detect_kernel<<<1, 256>>>((const unsigned*)ei, E);
    zero_kernel<<<512, 256>>>(N);
    edge_kernel<<<148, 256, SMEM_EDGE>>>(x, ei, ea, W1, b1, g1, be1, N, E);
    node_kernel<<<148, 256, SMEM_NODE>>>(x, W2, b2, g2, be2, out, N);
}

// round 6
// speedup vs baseline: 2.2794x; 1.3206x over previous
#include <cuda_runtime.h>
#include <cuda_bf16.h>
#include <cstdint>

#define DN   128
#define DE   64
#define NMAX 50000

__device__ float g_sums[(size_t)NMAX * DN];
__device__ float g_cnt[NMAX];
__device__ int   g_is64;

__device__ __forceinline__ float lrelu(float v) { return v > 0.f ? v : 0.01f * v; }

__device__ __forceinline__ uint32_t smem_u32(const void* p) {
    uint32_t a;
    asm("{ .reg .u64 t; cvta.to.shared.u64 t, %1; cvt.u32.u64 %0, t; }" : "=r"(a) : "l"(p));
    return a;
}

__device__ __forceinline__ void ldsm4(uint32_t addr, uint32_t r[4]) {
    asm volatile("ldmatrix.sync.aligned.m8n8.x4.shared.b16 {%0,%1,%2,%3}, [%4];"
                 : "=r"(r[0]), "=r"(r[1]), "=r"(r[2]), "=r"(r[3]) : "r"(addr));
}

__device__ __forceinline__ void mma16816(float c[4], const uint32_t a[4], const uint32_t b[2]) {
    asm volatile("mma.sync.aligned.m16n8k16.row.col.f32.bf16.bf16.f32 "
                 "{%0,%1,%2,%3}, {%4,%5,%6,%7}, {%8,%9}, {%0,%1,%2,%3};"
                 : "+f"(c[0]), "+f"(c[1]), "+f"(c[2]), "+f"(c[3])
                 : "r"(a[0]), "r"(a[1]), "r"(a[2]), "r"(a[3]), "r"(b[0]), "r"(b[1]));
}

__device__ __forceinline__ void split2(float v, unsigned short& h, unsigned short& l) {
    __nv_bfloat16 hb = __float2bfloat16(v);
    __nv_bfloat16 lb = __float2bfloat16(v - __bfloat162float(hb));
    h = *(unsigned short*)&hb;
    l = *(unsigned short*)&lb;
}
__device__ __forceinline__ void split4(float4 v, uint32_t& h01, uint32_t& h23,
                                       uint32_t& l01, uint32_t& l23) {
    __nv_bfloat162 a = __floats2bfloat162_rn(v.x, v.y);
    __nv_bfloat162 b = __floats2bfloat162_rn(v.z, v.w);
    __nv_bfloat162 c = __floats2bfloat162_rn(v.x - __low2float(a), v.y - __high2float(a));
    __nv_bfloat162 d = __floats2bfloat162_rn(v.z - __low2float(b), v.w - __high2float(b));
    h01 = *(uint32_t*)&a; h23 = *(uint32_t*)&b;
    l01 = *(uint32_t*)&c; l23 = *(uint32_t*)&d;
}

// 3-term split GEMM, warp tile 16x32. KB = row stride bytes, KS = K/16 steps.
template <int KB, int KS>
__device__ __forceinline__ void mma_core(uint32_t aH, uint32_t aL, uint32_t bH, uint32_t bL,
                                         int m0, int n0, int lane, float c[4][4])
{
#pragma unroll
    for (int nt = 0; nt < 4; ++nt)
#pragma unroll
        for (int j = 0; j < 4; ++j) c[nt][j] = 0.f;

    uint32_t rA = lane & 15;
    uint32_t kA = (lane >> 4) << 4;
    uint32_t xA = (rA & 7) << 4;
    uint32_t rB = ((lane >> 4) & 1) * 8 + (lane & 7);
    uint32_t kB = ((lane >> 3) & 1) << 4;
    uint32_t xB = (rB & 7) << 4;
    uint32_t aRH = aH + (m0 + rA) * KB;
    uint32_t aRL = aL + (m0 + rA) * KB;
    uint32_t bRH = bH + (n0 + rB) * KB;
    uint32_t bRL = bL + (n0 + rB) * KB;

#pragma unroll 2
    for (int ks = 0; ks < KS; ++ks) {
        uint32_t colA = (((uint32_t)ks * 32) | kA) ^ xA;
        uint32_t colB = (((uint32_t)ks * 32) | kB) ^ xB;
        uint32_t ah[4], al[4], bh[2][4], bl[2][4];
        ldsm4(aRH + colA, ah);
        ldsm4(aRL + colA, al);
#pragma unroll
        for (int p = 0; p < 2; ++p) {
            ldsm4(bRH + p * 16 * KB + colB, bh[p]);
            ldsm4(bRL + p * 16 * KB + colB, bl[p]);
        }
#pragma unroll
        for (int nt = 0; nt < 4; ++nt) {
            const uint32_t* bbh = &bh[nt >> 1][(nt & 1) * 2];
            const uint32_t* bbl = &bl[nt >> 1][(nt & 1) * 2];
            mma16816(c[nt], ah, bbh);
            mma16816(c[nt], al, bbh);
            mma16816(c[nt], ah, bbl);
        }
    }
}

// ---------------- small kernels -------------------------------------------------
__global__ void detect_kernel(const unsigned* __restrict__ w, int E)
{
    __shared__ unsigned accsh;
    if (threadIdx.x == 0) accsh = 0u;
    __syncthreads();
    int nscan = 4096; if (nscan > E) nscan = E;
    unsigned nz = 0;
    for (int i = threadIdx.x; i < nscan; i += blockDim.x) nz |= w[2 * i + 1];
#pragma unroll
    for (int o = 16; o > 0; o >>= 1) nz |= __shfl_xor_sync(0xffffffffu, nz, o);
    if ((threadIdx.x & 31) == 0) atomicOr(&accsh, nz);
    __syncthreads();
    if (threadIdx.x == 0) g_is64 = (accsh == 0u) ? 1 : 0;
}

__global__ void zero_kernel(int N)
{
    int tid = blockIdx.x * blockDim.x + threadIdx.x;
    int stride = gridDim.x * blockDim.x;
    float4 z = make_float4(0.f, 0.f, 0.f, 0.f);
    float4* s4 = (float4*)g_sums;
    int n4 = N * (DN / 4);
    for (int i = tid; i < n4; i += stride) s4[i] = z;
    for (int i = tid; i < N; i += stride) g_cnt[i] = 0.f;
}

// ---------------- edge kernel: 512 threads, 64-edge tiles, 2 syncs/tile ---------
#define E_BH 0
#define E_BL 49152
#define E_A  98304
#define E_AL 122880
#define E_C  147456
#define E_P  181248
#define SMEM_EDGE 182784
#define CSTRIDE 132

__global__ void __launch_bounds__(512, 1) edge_kernel(
    const float* __restrict__ x, const void* __restrict__ eidx,
    const float* __restrict__ ea, const float* __restrict__ W1,
    const float* __restrict__ b1, const float* __restrict__ g1,
    const float* __restrict__ be1, int N, int E)
{
    extern __shared__ char smem[];
    const uint32_t sb = smem_u32(smem);
    float* sC = (float*)(smem + E_C);
    float* sP = (float*)(smem + E_P);

    int tid = threadIdx.x, wid = tid >> 5, lane = tid & 31;
    int m0 = (wid >> 2) * 16, n0 = (wid & 3) * 32;

    // one-time: W1 (192 x 128) -> Bt[n][k] bf16 hi/lo, swizzled (row stride 384B)
    for (int i = tid; i < 192 * 32; i += 512) {
        int k = i >> 5, n4 = (i & 31) << 2;
        float4 w = *(const float4*)&W1[(size_t)k * DN + n4];
#pragma unroll
        for (int j = 0; j < 4; ++j) {
            int n = n4 + j;
            unsigned short h, l;
            split2((&w.x)[j], h, l);
            uint32_t a = sb + E_BH + n * 384 + (((uint32_t)(2 * k)) ^ (((uint32_t)(n & 7)) << 4));
            asm volatile("st.shared.b16 [%0], %1;" :: "r"(a), "h"(h));
            asm volatile("st.shared.b16 [%0], %1;" :: "r"(a + (E_BL - E_BH)), "h"(l));
        }
    }
    for (int i = tid; i < DN; i += 512) { sP[i] = b1[i]; sP[DN + i] = g1[i]; sP[2 * DN + i] = be1[i]; }

    const int is64 = g_is64;
    const long long* ei64 = (const long long*)eidx;
    const int*       ei32 = (const int*)eidx;

    int ntiles = (E + 63) >> 6;
    float4 v[6];

    // prologue: gather + convert tile t0
    int t = blockIdx.x;
    {
        int e0 = t << 6;
#pragma unroll
        for (int j = 0; j < 6; ++j) {
            int i = tid + (j << 9);
            int r = i / 48, q = i - r * 48;
            int e = e0 + r;
            float4 val = make_float4(0.f, 0.f, 0.f, 0.f);
            if (e < E) {
                if (q < 32) {
                    int ri = is64 ? (int)ei64[e] : ei32[e];
                    val = *(const float4*)&x[(size_t)ri * DN + q * 4];
                } else val = *(const float4*)&ea[(size_t)e * DE + (q - 32) * 4];
            }
            v[j] = val;
        }
#pragma unroll
        for (int j = 0; j < 6; ++j) {
            int i = tid + (j << 9);
            int r = i / 48, q = i - r * 48;
            uint32_t h01, h23, l01, l23;
            split4(v[j], h01, h23, l01, l23);
            uint32_t a = sb + E_A + r * 384 + (((uint32_t)(8 * q)) ^ (((uint32_t)(r & 7)) << 4));
            asm volatile("st.shared.v2.b32 [%0], {%1,%2};" :: "r"(a), "r"(h01), "r"(h23));
            asm volatile("st.shared.v2.b32 [%0], {%1,%2};" :: "r"(a + (E_AL - E_A)), "r"(l01), "r"(l23));
        }
    }
    __syncthreads();

    for (; t < ntiles; t += gridDim.x) {
        int tn = t + gridDim.x;
        // prefetch tile tn into registers (LDG hides under mma)
        if (tn < ntiles) {
            int e0 = tn << 6;
#pragma unroll
            for (int j = 0; j < 6; ++j) {
                int i = tid + (j << 9);
                int r = i / 48, q = i - r * 48;
                int e = e0 + r;
                float4 val = make_float4(0.f, 0.f, 0.f, 0.f);
                if (e < E) {
                    if (q < 32) {
                        int ri = is64 ? (int)ei64[e] : ei32[e];
                        val = *(const float4*)&x[(size_t)ri * DN + q * 4];
                    } else val = *(const float4*)&ea[(size_t)e * DE + (q - 32) * 4];
                }
                v[j] = val;
            }
        }

        float c[4][4];
        mma_core<384, 12>(sb + E_A, sb + E_AL, sb + E_BH, sb + E_BL, m0, n0, lane, c);

        // store C (separate buffer — own warp's A reads complete, no sync needed)
        int rlo = lane >> 2, cp = (lane & 3) * 2;
#pragma unroll
        for (int nt = 0; nt < 4; ++nt) {
            int row = m0 + rlo, col = n0 + nt * 8 + cp;
            *(float2*)&sC[row * CSTRIDE + col]       = make_float2(c[nt][0], c[nt][1]);
            *(float2*)&sC[(row + 8) * CSTRIDE + col] = make_float2(c[nt][2], c[nt][3]);
        }
        __syncthreads();   // C visible; all mma A-reads done

        // epilogue: warp owns rows [4*wid, 4*wid+4)
        {
            int e0 = t << 6;
            int c0 = lane * 4;
            float4 bb  = *(const float4*)&sP[c0];
            float4 gg  = *(const float4*)&sP[DN + c0];
            float4 beb = *(const float4*)&sP[2 * DN + c0];
#pragma unroll
            for (int j = 0; j < 4; ++j) {
                int r = wid * 4 + j;
                int e = e0 + r;
                float4 cv = *(const float4*)&sC[r * CSTRIDE + c0];
                float v0 = cv.x + bb.x, v1 = cv.y + bb.y, v2 = cv.z + bb.z, v3 = cv.w + bb.w;
                float s = v0 + v1 + v2 + v3;
                float q = fmaf(v0, v0, fmaf(v1, v1, fmaf(v2, v2, v3 * v3)));
#pragma unroll
                for (int o = 16; o > 0; o >>= 1) {
                    s += __shfl_xor_sync(0xffffffffu, s, o);
                    q += __shfl_xor_sync(0xffffffffu, q, o);
                }
                const float inv = 0.0078125f;
                float mean = s * inv;
                float var  = fmaf(q, inv, -mean * mean);
                float rstd = rsqrtf(var + 1e-5f);
                float o0 = lrelu(fmaf((v0 - mean) * rstd, gg.x, beb.x));
                float o1 = lrelu(fmaf((v1 - mean) * rstd, gg.y, beb.y));
                float o2 = lrelu(fmaf((v2 - mean) * rstd, gg.z, beb.z));
                float o3 = lrelu(fmaf((v3 - mean) * rstd, gg.w, beb.w));
                if (e < E) {
                    int ci = is64 ? (int)ei64[(size_t)E + e] : ei32[E + e];
                    float* p = g_sums + (size_t)ci * DN + c0;
                    asm volatile("red.global.add.v4.f32 [%0], {%1,%2,%3,%4};"
                                 :: "l"(p), "f"(o0), "f"(o1), "f"(o2), "f"(o3) : "memory");
                    if (lane == 0) atomicAdd(g_cnt + ci, 1.0f);
                }
            }
        }

        // convert prefetched regs -> A(tn)  (A free: sync above covered mma reads)
        if (tn < ntiles) {
#pragma unroll
            for (int j = 0; j < 6; ++j) {
                int i = tid + (j << 9);
                int r = i / 48, q = i - r * 48;
                uint32_t h01, h23, l01, l23;
                split4(v[j], h01, h23, l01, l23);
                uint32_t a = sb + E_A + r * 384 + (((uint32_t)(8 * q)) ^ (((uint32_t)(r & 7)) << 4));
                asm volatile("st.shared.v2.b32 [%0], {%1,%2};" :: "r"(a), "r"(h01), "r"(h23));
                asm volatile("st.shared.v2.b32 [%0], {%1,%2};" :: "r"(a + (E_AL - E_A)), "r"(l01), "r"(l23));
            }
        }
        __syncthreads();   // A(tn) ready; C reads done before next overwrite
    }
}

// ---------------- node kernel: 512 threads, same pipeline -----------------------
#define N_BH 0
#define N_BL 32768
#define N_A  65536
#define N_AL 81920
#define N_C  98304
#define N_P  132096
#define SMEM_NODE 133632

__global__ void __launch_bounds__(512, 1) node_kernel(
    const float* __restrict__ x, const float* __restrict__ W2,
    const float* __restrict__ b2, const float* __restrict__ g2,
    const float* __restrict__ be2, float* __restrict__ out, int N)
{
    extern __shared__ char smem[];
    const uint32_t sb = smem_u32(smem);
    float* sC = (float*)(smem + N_C);
    float* sP = (float*)(smem + N_P);

    int tid = threadIdx.x, wid = tid >> 5, lane = tid & 31;
    int m0 = (wid >> 2) * 16, n0 = (wid & 3) * 32;

    for (int i = tid; i < 128 * 32; i += 512) {
        int k = i >> 5, n4 = (i & 31) << 2;
        float4 w = *(const float4*)&W2[(size_t)k * DN + n4];
#pragma unroll
        for (int j = 0; j < 4; ++j) {
            int n = n4 + j;
            unsigned short h, l;
            split2((&w.x)[j], h, l);
            uint32_t a = sb + N_BH + n * 256 + (((uint32_t)(2 * k)) ^ (((uint32_t)(n & 7)) << 4));
            asm volatile("st.shared.b16 [%0], %1;" :: "r"(a), "h"(h));
            asm volatile("st.shared.b16 [%0], %1;" :: "r"(a + (N_BL - N_BH)), "h"(l));
        }
    }
    for (int i = tid; i < DN; i += 512) { sP[i] = b2[i]; sP[DN + i] = g2[i]; sP[2 * DN + i] = be2[i]; }

    int ntiles = (N + 63) >> 6;
    float4 v[4];

    int t = blockIdx.x;
    {
        int nb = t << 6;
#pragma unroll
        for (int j = 0; j < 4; ++j) {
            int i = tid + (j << 9);
            int r = i >> 5, q = i & 31;
            int n = nb + r;
            float4 val = make_float4(0.f, 0.f, 0.f, 0.f);
            if (n < N) {
                float sc = 1.0f / fmaxf(g_cnt[n], 1.0f);
                val = *(const float4*)&g_sums[(size_t)n * DN + q * 4];
                val.x *= sc; val.y *= sc; val.z *= sc; val.w *= sc;
            }
            v[j] = val;
        }
#pragma unroll
        for (int j = 0; j < 4; ++j) {
            int i = tid + (j << 9);
            int r = i >> 5, q = i & 31;
            uint32_t h01, h23, l01, l23;
            split4(v[j], h01, h23, l01, l23);
            uint32_t a = sb + N_A + r * 256 + (((uint32_t)(8 * q)) ^ (((uint32_t)(r & 7)) << 4));
            asm volatile("st.shared.v2.b32 [%0], {%1,%2};" :: "r"(a), "r"(h01), "r"(h23));
            asm volatile("st.shared.v2.b32 [%0], {%1,%2};" :: "r"(a + (N_AL - N_A)), "r"(l01), "r"(l23));
        }
    }
    __syncthreads();

    for (; t < ntiles; t += gridDim.x) {
        int tn = t + gridDim.x;
        if (tn < ntiles) {
            int nb = tn << 6;
#pragma unroll
            for (int j = 0; j < 4; ++j) {
                int i = tid + (j << 9);
                int r = i >> 5, q = i & 31;
                int n = nb + r;
                float4 val = make_float4(0.f, 0.f, 0.f, 0.f);
                if (n < N) {
                    float sc = 1.0f / fmaxf(g_cnt[n], 1.0f);
                    val = *(const float4*)&g_sums[(size_t)n * DN + q * 4];
                    val.x *= sc; val.y *= sc; val.z *= sc; val.w *= sc;
                }
                v[j] = val;
            }
        }

        float c[4][4];
        mma_core<256, 8>(sb + N_A, sb + N_AL, sb + N_BH, sb + N_BL, m0, n0, lane, c);

        int rlo = lane >> 2, cp = (lane & 3) * 2;
#pragma unroll
        for (int nt = 0; nt < 4; ++nt) {
            int row = m0 + rlo, col = n0 + nt * 8 + cp;
            *(float2*)&sC[row * CSTRIDE + col]       = make_float2(c[nt][0], c[nt][1]);
            *(float2*)&sC[(row + 8) * CSTRIDE + col] = make_float2(c[nt][2], c[nt][3]);
        }
        __syncthreads();

        {
            int nb = t << 6;
            int c0 = lane * 4;
            float4 bb  = *(const float4*)&sP[c0];
            float4 gg  = *(const float4*)&sP[DN + c0];
            float4 beb = *(const float4*)&sP[2 * DN + c0];
#pragma unroll
            for (int j = 0; j < 4; ++j) {
                int r = wid * 4 + j;
                int n = nb + r;
                float4 cv = *(const float4*)&sC[r * CSTRIDE + c0];
                float v0 = cv.x + bb.x, v1 = cv.y + bb.y, v2 = cv.z + bb.z, v3 = cv.w + bb.w;
                float s = v0 + v1 + v2 + v3;
                float q = fmaf(v0, v0, fmaf(v1, v1, fmaf(v2, v2, v3 * v3)));
#pragma unroll
                for (int o = 16; o > 0; o >>= 1) {
                    s += __shfl_xor_sync(0xffffffffu, s, o);
                    q += __shfl_xor_sync(0xffffffffu, q, o);
                }
                const float inv = 0.0078125f;
                float mean = s * inv;
                float var  = fmaf(q, inv, -mean * mean);
                float rstd = rsqrtf(var + 1e-5f);
                float o0 = lrelu(fmaf((v0 - mean) * rstd, gg.x, beb.x));
                float o1 = lrelu(fmaf((v1 - mean) * rstd, gg.y, beb.y));
                float o2 = lrelu(fmaf((v2 - mean) * rstd, gg.z, beb.z));
                float o3 = lrelu(fmaf((v3 - mean) * rstd, gg.w, beb.w));
                if (n < N) {
                    float4 xr = *(const float4*)&x[(size_t)n * DN + c0];
                    o0 = lrelu(o0 + xr.x);
                    o1 = lrelu(o1 + xr.y);
                    o2 = lrelu(o2 + xr.z);
                    o3 = lrelu(o3 + xr.w);
                    *(float4*)&out[(size_t)n * DN + c0] = make_float4(o0, o1, o2, o3);
                }
            }
        }

        if (tn < ntiles) {
#pragma unroll
            for (int j = 0; j < 4; ++j) {
                int i = tid + (j << 9);
                int r = i >> 5, q = i & 31;
                uint32_t h01, h23, l01, l23;
                split4(v[j], h01, h23, l01, l23);
                uint32_t a = sb + N_A + r * 256 + (((uint32_t)(8 * q)) ^ (((uint32_t)(r & 7)) << 4));
                asm volatile("st.shared.v2.b32 [%0], {%1,%2};" :: "r"(a), "r"(h01), "r"(h23));
                asm volatile("st.shared.v2.b32 [%0], {%1,%2};" :: "r"(a + (N_AL - N_A)), "r"(l01), "r"(l23));
            }
        }
        __syncthreads();
    }
}

// ---------------- launch ----------------------------------------------------------
extern "C" void kernel_launch(void* const* d_in, const int* in_sizes, int n_in,
                              void* d_out, int out_size)
{
    const float* x   = (const float*)d_in[0];
    const void*  ei  = d_in[1];
    const float* ea  = (const float*)d_in[2];
    const float* W1  = (const float*)d_in[3];
    const float* b1  = (const float*)d_in[4];
    const float* g1  = (const float*)d_in[5];
    const float* be1 = (const float*)d_in[6];
    const float* W2  = (const float*)d_in[7];
    const float* b2  = (const float*)d_in[8];
    const float* g2  = (const float*)d_in[9];
    const float* be2 = (const float*)d_in[10];
    float* out = (float*)d_out;

    int N = in_sizes[0] / DN;
    int E = in_sizes[2] / DE;

    cudaFuncSetAttribute(edge_kernel, cudaFuncAttributeMaxDynamicSharedMemorySize, SMEM_EDGE);
    cudaFuncSetAttribute(node_kernel, cudaFuncAttributeMaxDynamicSharedMemorySize, SMEM_NODE);

    detect_kernel<<<1, 256>>>((const unsigned*)ei, E);
    zero_kernel<<<512, 256>>>(N);
    edge_kernel<<<148, 512, SMEM_EDGE>>>(x, ei, ea, W1, b1, g1, be1, N, E);
    node_kernel<<<148, 512, SMEM_NODE>>>(x, W2, b2, g2, be2, out, N);
}